// round 8
// baseline (speedup 1.0000x reference)
#include <cuda_runtime.h>
#include <cuda_bf16.h>
#include <math.h>

// Problem constants: NC=1000, K=8, N=32, D=128  -> G = 8000 groups
#define G_TOT 8000
#define NPT   32
#define DIM   128
#define ITERS 20
#define TOLF  1e-6f
#define EPSF  1e-7f
#define CLIPF 1e-7f
#define PITCH 33          // smem transpose pitch (floats) — conflict-free both ways

// Static scratch (no runtime allocation)
__device__ float g_vnorm[(size_t)ITERS * G_TOT];
__device__ float g_lossT[(size_t)(ITERS + 1) * G_TOT];
__device__ float g_maxv[ITERS];

using u64 = unsigned long long;

// ---- packed f32x2 helpers ----
__device__ __forceinline__ u64 pk2(float a, float b) {
    u64 r; asm("mov.b64 %0, {%1,%2};" : "=l"(r) : "f"(a), "f"(b)); return r;
}
__device__ __forceinline__ float2 upk2(u64 v) {
    float2 r; asm("mov.b64 {%0,%1}, %2;" : "=f"(r.x), "=f"(r.y) : "l"(v)); return r;
}
__device__ __forceinline__ u64 ffma2(u64 a, u64 b, u64 c) {
    u64 d; asm("fma.rn.f32x2 %0, %1, %2, %3;" : "=l"(d) : "l"(a), "l"(b), "l"(c)); return d;
}
__device__ __forceinline__ u64 fmul2(u64 a, u64 b) {
    u64 d; asm("mul.rn.f32x2 %0, %1, %2;" : "=l"(d) : "l"(a), "l"(b)); return d;
}
__device__ __forceinline__ u64 fadd2(u64 a, u64 b) {
    u64 d; asm("add.rn.f32x2 %0, %1, %2;" : "=l"(d) : "l"(a), "l"(b)); return d;
}

__device__ __forceinline__ float warpSum(float v) {
    #pragma unroll
    for (int o = 16; o > 0; o >>= 1)
        v += __shfl_xor_sync(0xffffffffu, v, o);
    return v;
}
// packed pairwise warp sum (two reductions for the price of one butterfly)
__device__ __forceinline__ u64 warpSum2(u64 v) {
    #pragma unroll
    for (int o = 16; o > 0; o >>= 1)
        v = fadd2(v, __shfl_xor_sync(0xffffffffu, v, o));
    return v;
}

// Sum lane L's row of the transpose buffer: 32 LDS.32 (conflict-free) + add tree
__device__ __forceinline__ float rowSum(const float* tb, int L) {
    const float* r = tb + L * PITCH;
    float a = 0.f, b = 0.f, c = 0.f, d = 0.f;
    #pragma unroll
    for (int k = 0; k < 8; k++) {
        a += r[4 * k + 0];
        b += r[4 * k + 1];
        c += r[4 * k + 2];
        d += r[4 * k + 3];
    }
    return (a + b) + (c + d);
}

// ---------------------------------------------------------------------------
// Kernel 1: fused normalize + 20 Karcher iterations + per-candidate loss.
// One warp per group. X in registers (column layout: lane owns dims 4L..4L+3
// of all 32 points, packed f32x2). Per-point scalars reached via a smem
// 32x32 transpose (pitch 33, conflict-free). mu carried unnormalized with a
// deferred scalar s = 1/||m^|| applied after the transpose-reduce.
// ---------------------------------------------------------------------------
__global__ void __launch_bounds__(32, 14) karcher_kernel(const float* __restrict__ X) {
    __shared__ float tb[NPT * PITCH];

    const int g    = blockIdx.x;
    const int lane = threadIdx.x;
    const float4* __restrict__ Xg = (const float4*)X + (size_t)g * (NPT * DIM / 4);

    u64 xa[NPT], xb[NPT];   // point n: dims 4L..4L+1 in xa[n], 4L+2..4L+3 in xb[n]

    // Load (coalesced LDG.128) + per-point squared-norm partials -> smem
    #pragma unroll
    for (int n = 0; n < NPT; n++) {
        float4 v = Xg[n * 32 + lane];
        xa[n] = pk2(v.x, v.y);
        xb[n] = pk2(v.z, v.w);
        u64 q = ffma2(xb[n], xb[n], fmul2(xa[n], xa[n]));
        float2 qf = upk2(q);
        tb[n * PITCH + lane] = qf.x + qf.y;
    }
    __syncwarp();
    float nq  = rowSum(tb, lane);            // ||x_lane||^2
    __syncwarp();                            // reads done before buffer reuse
    float inv = rsqrtf(fmaxf(nq, 1e-24f));   // == 1/max(||x||,1e-12)

    #pragma unroll
    for (int n = 0; n < NPT; n++) {
        float invn = __shfl_sync(0xffffffffu, inv, n);
        u64 i2 = pk2(invn, invn);
        xa[n] = fmul2(xa[n], i2);
        xb[n] = fmul2(xb[n], i2);
    }

    // m^0 = sum(Xn)  (direction of mean; scale folded into s)
    u64 ma = 0ull, mb = 0ull;
    #pragma unroll
    for (int n = 0; n < NPT; n++) { ma = fadd2(ma, xa[n]); mb = fadd2(mb, xb[n]); }
    float s;
    {
        u64 q = ffma2(mb, mb, fmul2(ma, ma));
        float2 qf = upk2(q);
        s = rsqrtf(fmaxf(warpSum(qf.x + qf.y), 1e-24f));
    }

    const u64 K32 = pk2(1.0f / 32.0f, 1.0f / 32.0f);

    #pragma unroll 1
    for (int it = 0; it < ITERS; ++it) {
        // ---- raw dots: partials -> smem transpose -> lane = point
        #pragma unroll
        for (int n = 0; n < NPT; n++) {
            u64 t = ffma2(ma, xa[n], fmul2(mb, xb[n]));
            float2 tf = upk2(t);
            tb[n * PITCH + lane] = tf.x + tf.y;
        }
        __syncwarp();
        float raw = rowSum(tb, lane);
        __syncwarp();                        // reads done before next iter's writes

        float dot   = s * raw;               // apply deferred normalization
        float dc    = fminf(fmaxf(dot, -1.0f + CLIPF), 1.0f - CLIPF);
        float theta = acosf(dc);
        float st    = fmaxf(sqrtf(fmaf(-dc, dc, 1.0f)), EPSF);  // sin(acos(dc))
        float w     = __fdividef(theta, st);

        // c = sum w*dot and loss = sum theta^2 in ONE packed butterfly
        u64 pr = warpSum2(pk2(w * dot, theta * theta));
        float2 cl = upk2(pr);
        if (lane == 0) g_lossT[(size_t)it * G_TOT + g] = cl.y;

        // ---- s1[d] = sum_n w_n * x[n][d]
        u64 s1a = 0ull, s1b = 0ull;
        #pragma unroll
        for (int n = 0; n < NPT; n++) {
            float wn = __shfl_sync(0xffffffffu, w, n);
            u64 w2 = pk2(wn, wn);
            s1a = ffma2(w2, xa[n], s1a);
            s1b = ffma2(w2, xb[n], s1b);
        }

        // v = (s1 - c*mu)/32,  mu = s*m^  ->  (s1 - (c*s)*m^)/32
        float ncs = -cl.x * s;
        u64 nc2 = pk2(ncs, ncs);
        u64 va = fmul2(ffma2(nc2, ma, s1a), K32);
        u64 vb = fmul2(ffma2(nc2, mb, s1b), K32);
        u64 vv = ffma2(vb, vb, fmul2(va, va));
        float2 vf = upk2(vv);
        float vq = warpSum(vf.x + vf.y);
        float vnorm = fmaxf(sqrtf(vq), EPSF);
        if (lane == 0) g_vnorm[(size_t)it * G_TOT + g] = vnorm;

        // exp map: m^' = (cos(a)*s)*m^ + (sin(a)/a)*v   (renorm deferred via s')
        float ca = __cosf(vnorm);
        float k  = __fdividef(__sinf(vnorm), vnorm);
        float cas = ca * s;
        u64 cas2 = pk2(cas, cas), k2 = pk2(k, k);
        ma = ffma2(cas2, ma, fmul2(k2, va));
        mb = ffma2(cas2, mb, fmul2(k2, vb));

        // s' = 1/||m^'||  — warpSum latency overlaps next dot pass (s used late)
        u64 mm = ffma2(mb, mb, fmul2(ma, ma));
        float2 mf = upk2(mm);
        s = rsqrtf(fmaxf(warpSum(mf.x + mf.y), 1e-24f));
    }

    // ---- loss candidate t = 20 (never frozen)
    #pragma unroll
    for (int n = 0; n < NPT; n++) {
        u64 t = ffma2(ma, xa[n], fmul2(mb, xb[n]));
        float2 tf = upk2(t);
        tb[n * PITCH + lane] = tf.x + tf.y;
    }
    __syncwarp();
    float raw = rowSum(tb, lane);
    float dc = fminf(fmaxf(s * raw, -1.0f + CLIPF), 1.0f - CLIPF);
    float th = acosf(dc);
    float ls = warpSum(th * th);
    if (lane == 0) g_lossT[(size_t)ITERS * G_TOT + g] = ls;
}

// ---------------------------------------------------------------------------
// Kernel 2: per-iteration max over groups of vnorm
// ---------------------------------------------------------------------------
__global__ void max_kernel() {
    __shared__ float sh[256];
    const int it = blockIdx.x;
    float m = 0.f;
    for (int i = threadIdx.x; i < G_TOT; i += 256)
        m = fmaxf(m, g_vnorm[(size_t)it * G_TOT + i]);
    sh[threadIdx.x] = m;
    __syncthreads();
    for (int s = 128; s > 0; s >>= 1) {
        if (threadIdx.x < s) sh[threadIdx.x] = fmaxf(sh[threadIdx.x], sh[threadIdx.x + s]);
        __syncthreads();
    }
    if (threadIdx.x == 0) g_maxv[it] = sh[0];
}

// ---------------------------------------------------------------------------
// Kernel 3: t* selection + deterministic mean of the selected losses
// ---------------------------------------------------------------------------
__global__ void final_kernel(float* __restrict__ out) {
    __shared__ float sh[1024];
    __shared__ int ts;
    if (threadIdx.x == 0) {
        int t = ITERS;
        for (int i = 0; i < ITERS; i++)
            if (g_maxv[i] < TOLF) { t = i; break; }
        ts = t;
    }
    __syncthreads();
    const int t = ts;
    float acc = 0.f;
    for (int i = threadIdx.x; i < G_TOT; i += 1024)
        acc += g_lossT[(size_t)t * G_TOT + i];
    sh[threadIdx.x] = acc;
    __syncthreads();
    for (int s = 512; s > 0; s >>= 1) {
        if (threadIdx.x < s) sh[threadIdx.x] += sh[threadIdx.x + s];
        __syncthreads();
    }
    if (threadIdx.x == 0) out[0] = sh[0] * (1.0f / (float)G_TOT);
}

// ---------------------------------------------------------------------------
extern "C" void kernel_launch(void* const* d_in, const int* in_sizes, int n_in,
                              void* d_out, int out_size) {
    const float* X = (const float*)d_in[0];
    float* out = (float*)d_out;

    karcher_kernel<<<G_TOT, 32>>>(X);
    max_kernel<<<ITERS, 256>>>();
    final_kernel<<<1, 1024>>>(out);
}

// round 9
// speedup vs baseline: 2.3649x; 2.3649x over previous
#include <cuda_runtime.h>
#include <cuda_bf16.h>
#include <math.h>

// Problem constants: NC=1000, K=8, N=32, D=128  -> G = 8000 groups
#define G_TOT 8000
#define NPT   32
#define DIM   128
#define ITERS 20
#define TOLF  1e-6f
#define EPSF  1e-7f
#define CLIPF 1e-7f
#define PITCH 33          // smem transpose pitch (floats) — conflict-free both ways

// Static scratch (no runtime allocation)
__device__ float g_vnorm[(size_t)ITERS * G_TOT];
__device__ float g_lossT[(size_t)(ITERS + 1) * G_TOT];
__device__ float g_maxv[ITERS];

using u64 = unsigned long long;

// ---- packed f32x2 helpers ----
__device__ __forceinline__ u64 pk2(float a, float b) {
    u64 r; asm("mov.b64 %0, {%1,%2};" : "=l"(r) : "f"(a), "f"(b)); return r;
}
__device__ __forceinline__ float2 upk2(u64 v) {
    float2 r; asm("mov.b64 {%0,%1}, %2;" : "=f"(r.x), "=f"(r.y) : "l"(v)); return r;
}
__device__ __forceinline__ u64 ffma2(u64 a, u64 b, u64 c) {
    u64 d; asm("fma.rn.f32x2 %0, %1, %2, %3;" : "=l"(d) : "l"(a), "l"(b), "l"(c)); return d;
}
__device__ __forceinline__ u64 fmul2(u64 a, u64 b) {
    u64 d; asm("mul.rn.f32x2 %0, %1, %2;" : "=l"(d) : "l"(a), "l"(b)); return d;
}
__device__ __forceinline__ u64 fadd2(u64 a, u64 b) {
    u64 d; asm("add.rn.f32x2 %0, %1, %2;" : "=l"(d) : "l"(a), "l"(b)); return d;
}

__device__ __forceinline__ float warpSum(float v) {
    #pragma unroll
    for (int o = 16; o > 0; o >>= 1)
        v += __shfl_xor_sync(0xffffffffu, v, o);
    return v;
}
// packed pairwise warp sum (two reductions in one butterfly)
__device__ __forceinline__ u64 warpSum2(u64 v) {
    #pragma unroll
    for (int o = 16; o > 0; o >>= 1)
        v = fadd2(v, __shfl_xor_sync(0xffffffffu, v, o));
    return v;
}

// Sum lane L's row of the transpose buffer: 32 LDS.32 (conflict-free) + add tree
__device__ __forceinline__ float rowSum(const float* tb, int L) {
    const float* r = tb + L * PITCH;
    float a = 0.f, b = 0.f, c = 0.f, d = 0.f;
    #pragma unroll
    for (int k = 0; k < 8; k++) {
        a += r[4 * k + 0];
        b += r[4 * k + 1];
        c += r[4 * k + 2];
        d += r[4 * k + 3];
    }
    return (a + b) + (c + d);
}

// ---------------------------------------------------------------------------
// Kernel 1: fused normalize + 20 Karcher iterations + per-candidate loss.
// One warp per group. X in registers (column layout: lane owns dims 4L..4L+3
// of all 32 points, packed f32x2). Per-point scalars via a smem 32x32
// transpose (pitch 33). mu carried unnormalized; s = 1/||m^|| deferred.
// NOTE: minBlocks=12 -> reg ceiling ~170 (natural use ~145). 14 forced a
// 128-reg cap and spilled the 128-reg X tile (R8 regression).
// ---------------------------------------------------------------------------
__global__ void __launch_bounds__(32, 12) karcher_kernel(const float* __restrict__ X) {
    __shared__ float tb[NPT * PITCH];

    const int g    = blockIdx.x;
    const int lane = threadIdx.x;
    const float4* __restrict__ Xg = (const float4*)X + (size_t)g * (NPT * DIM / 4);

    u64 xa[NPT], xb[NPT];   // point n: dims 4L..4L+1 in xa[n], 4L+2..4L+3 in xb[n]

    // Load (coalesced LDG.128) + per-point squared-norm partials -> smem
    #pragma unroll
    for (int n = 0; n < NPT; n++) {
        float4 v = Xg[n * 32 + lane];
        xa[n] = pk2(v.x, v.y);
        xb[n] = pk2(v.z, v.w);
        u64 q = ffma2(xb[n], xb[n], fmul2(xa[n], xa[n]));
        float2 qf = upk2(q);
        tb[n * PITCH + lane] = qf.x + qf.y;
    }
    __syncwarp();
    float nq  = rowSum(tb, lane);            // ||x_lane||^2
    __syncwarp();                            // reads done before buffer reuse
    float inv = rsqrtf(fmaxf(nq, 1e-24f));   // == 1/max(||x||,1e-12)

    #pragma unroll
    for (int n = 0; n < NPT; n++) {
        float invn = __shfl_sync(0xffffffffu, inv, n);
        u64 i2 = pk2(invn, invn);
        xa[n] = fmul2(xa[n], i2);
        xb[n] = fmul2(xb[n], i2);
    }

    // m^0 = sum(Xn)  (direction of mean; scale folded into s)
    u64 ma = 0ull, mb = 0ull;
    #pragma unroll
    for (int n = 0; n < NPT; n++) { ma = fadd2(ma, xa[n]); mb = fadd2(mb, xb[n]); }
    float s;
    {
        u64 q = ffma2(mb, mb, fmul2(ma, ma));
        float2 qf = upk2(q);
        s = rsqrtf(fmaxf(warpSum(qf.x + qf.y), 1e-24f));
    }

    const u64 K32 = pk2(1.0f / 32.0f, 1.0f / 32.0f);

    #pragma unroll 1
    for (int it = 0; it < ITERS; ++it) {
        // ---- raw dots: partials -> smem transpose -> lane = point
        #pragma unroll
        for (int n = 0; n < NPT; n++) {
            u64 t = ffma2(ma, xa[n], fmul2(mb, xb[n]));
            float2 tf = upk2(t);
            tb[n * PITCH + lane] = tf.x + tf.y;
        }
        __syncwarp();
        float raw = rowSum(tb, lane);
        __syncwarp();                        // reads done before next iter's writes

        float dot   = s * raw;               // apply deferred normalization
        float dc    = fminf(fmaxf(dot, -1.0f + CLIPF), 1.0f - CLIPF);
        float theta = acosf(dc);
        float st    = fmaxf(sqrtf(fmaf(-dc, dc, 1.0f)), EPSF);  // sin(acos(dc))
        float w     = __fdividef(theta, st);

        // c = sum w*dot and loss = sum theta^2 in ONE packed butterfly
        u64 pr = warpSum2(pk2(w * dot, theta * theta));
        float2 cl = upk2(pr);
        if (lane == 0) g_lossT[(size_t)it * G_TOT + g] = cl.y;

        // ---- s1[d] = sum_n w_n * x[n][d]
        u64 s1a = 0ull, s1b = 0ull;
        #pragma unroll
        for (int n = 0; n < NPT; n++) {
            float wn = __shfl_sync(0xffffffffu, w, n);
            u64 w2 = pk2(wn, wn);
            s1a = ffma2(w2, xa[n], s1a);
            s1b = ffma2(w2, xb[n], s1b);
        }

        // v = (s1 - c*mu)/32,  mu = s*m^  ->  (s1 - (c*s)*m^)/32
        float ncs = -cl.x * s;
        u64 nc2 = pk2(ncs, ncs);
        u64 va = fmul2(ffma2(nc2, ma, s1a), K32);
        u64 vb = fmul2(ffma2(nc2, mb, s1b), K32);
        u64 vv = ffma2(vb, vb, fmul2(va, va));
        float2 vf = upk2(vv);
        float vq = warpSum(vf.x + vf.y);
        float vnorm = fmaxf(sqrtf(vq), EPSF);
        if (lane == 0) g_vnorm[(size_t)it * G_TOT + g] = vnorm;

        // exp map: m^' = (cos(a)*s)*m^ + (sin(a)/a)*v   (renorm deferred via s')
        float ca = __cosf(vnorm);
        float k  = __fdividef(__sinf(vnorm), vnorm);
        float cas = ca * s;
        u64 cas2 = pk2(cas, cas), k2 = pk2(k, k);
        ma = ffma2(cas2, ma, fmul2(k2, va));
        mb = ffma2(cas2, mb, fmul2(k2, vb));

        // s' = 1/||m^'||  — warpSum latency overlaps next dot pass (s used late)
        u64 mm = ffma2(mb, mb, fmul2(ma, ma));
        float2 mf = upk2(mm);
        s = rsqrtf(fmaxf(warpSum(mf.x + mf.y), 1e-24f));
    }

    // ---- loss candidate t = 20 (never frozen)
    #pragma unroll
    for (int n = 0; n < NPT; n++) {
        u64 t = ffma2(ma, xa[n], fmul2(mb, xb[n]));
        float2 tf = upk2(t);
        tb[n * PITCH + lane] = tf.x + tf.y;
    }
    __syncwarp();
    float raw = rowSum(tb, lane);
    float dc = fminf(fmaxf(s * raw, -1.0f + CLIPF), 1.0f - CLIPF);
    float th = acosf(dc);
    float ls = warpSum(th * th);
    if (lane == 0) g_lossT[(size_t)ITERS * G_TOT + g] = ls;
}

// ---------------------------------------------------------------------------
// Kernel 2: per-iteration max over groups of vnorm
// ---------------------------------------------------------------------------
__global__ void max_kernel() {
    __shared__ float sh[256];
    const int it = blockIdx.x;
    float m = 0.f;
    for (int i = threadIdx.x; i < G_TOT; i += 256)
        m = fmaxf(m, g_vnorm[(size_t)it * G_TOT + i]);
    sh[threadIdx.x] = m;
    __syncthreads();
    for (int s = 128; s > 0; s >>= 1) {
        if (threadIdx.x < s) sh[threadIdx.x] = fmaxf(sh[threadIdx.x], sh[threadIdx.x + s]);
        __syncthreads();
    }
    if (threadIdx.x == 0) g_maxv[it] = sh[0];
}

// ---------------------------------------------------------------------------
// Kernel 3: t* selection + deterministic mean of the selected losses
// ---------------------------------------------------------------------------
__global__ void final_kernel(float* __restrict__ out) {
    __shared__ float sh[1024];
    __shared__ int ts;
    if (threadIdx.x == 0) {
        int t = ITERS;
        for (int i = 0; i < ITERS; i++)
            if (g_maxv[i] < TOLF) { t = i; break; }
        ts = t;
    }
    __syncthreads();
    const int t = ts;
    float acc = 0.f;
    for (int i = threadIdx.x; i < G_TOT; i += 1024)
        acc += g_lossT[(size_t)t * G_TOT + i];
    sh[threadIdx.x] = acc;
    __syncthreads();
    for (int s = 512; s > 0; s >>= 1) {
        if (threadIdx.x < s) sh[threadIdx.x] += sh[threadIdx.x + s];
        __syncthreads();
    }
    if (threadIdx.x == 0) out[0] = sh[0] * (1.0f / (float)G_TOT);
}

// ---------------------------------------------------------------------------
extern "C" void kernel_launch(void* const* d_in, const int* in_sizes, int n_in,
                              void* d_out, int out_size) {
    const float* X = (const float*)d_in[0];
    float* out = (float*)d_out;

    karcher_kernel<<<G_TOT, 32>>>(X);
    max_kernel<<<ITERS, 256>>>();
    final_kernel<<<1, 1024>>>(out);
}